// round 2
// baseline (speedup 1.0000x reference)
#include <cuda_runtime.h>
#include <stdint.h>
#include <math.h>

#define BATCH 512
#define OUTF  1024
#define KPOS  256
#define NIDX  4096
#define BTILE 4

// ---- device scratch (no allocations allowed) ----
__device__ uint8_t  g_tab[NIDX * NIDX];      // 16MB compact u8 table
__device__ uint16_t g_wT[KPOS * OUTF];       // weight indices transposed [k][o]
__device__ int      g_mode;                  // 0=u8, 1=int32, 2=float32

// -------- detect how the table was uploaded --------
__global__ void detect_kernel(const uint32_t* __restrict__ w) {
    int lane = threadIdx.x;
    bool small = true, isf = true;
    for (int i = lane; i < 1024; i += 32) {
        uint32_t x = w[i];
        small = small && (x < 256u);
        float f = __uint_as_float(x);
        isf = isf && (f >= 0.0f) && (f < 256.0f) && (f == truncf(f));
    }
    small = __all_sync(0xFFFFFFFFu, small);
    isf   = __all_sync(0xFFFFFFFFu, isf);
    if (lane == 0) g_mode = small ? 1 : (isf ? 2 : 0);
}

// -------- compact table -> u8 (16 bytes per thread) --------
__global__ void convert_kernel(const void* __restrict__ table) {
    const int mode = g_mode;
    const int t = blockIdx.x * blockDim.x + threadIdx.x;  // 1M threads
    uint4 o;
    if (mode == 1) {
        const int4* src = (const int4*)table;
        uint32_t p[4];
#pragma unroll
        for (int s = 0; s < 4; s++) {
            int4 v = src[t * 4 + s];
            p[s] = (uint32_t)(v.x & 255) | ((uint32_t)(v.y & 255) << 8) |
                   ((uint32_t)(v.z & 255) << 16) | ((uint32_t)(v.w & 255) << 24);
        }
        o = make_uint4(p[0], p[1], p[2], p[3]);
    } else if (mode == 2) {
        const float4* src = (const float4*)table;
        uint32_t p[4];
#pragma unroll
        for (int s = 0; s < 4; s++) {
            float4 v = src[t * 4 + s];
            p[s] = (uint32_t)v.x | ((uint32_t)v.y << 8) |
                   ((uint32_t)v.z << 16) | ((uint32_t)v.w << 24);
        }
        o = make_uint4(p[0], p[1], p[2], p[3]);
    } else {
        o = ((const uint4*)table)[t];
    }
    *(uint4*)&g_tab[t * 16] = o;
}

// -------- pre-pass: transpose + clamp weight indices to [k][o] u16 --------
__global__ void prep_w_kernel(const int* __restrict__ w_idx) {
    int t = blockIdx.x * blockDim.x + threadIdx.x;
    if (t < OUTF * KPOS) {
        int o = t / KPOS;
        int k = t - o * KPOS;
        int v = w_idx[t];
        v = v < 0 ? 0 : (v > NIDX - 1 ? NIDX - 1 : v);
        g_wT[k * OUTF + o] = (uint16_t)v;
    }
}

// -------- main kernel: batch-interleaved smem gather --------
// One CTA = 4 batches x all 1024 outputs. thread o = threadIdx.x.
// Per k: rows g_tab[i[b0+j,k], :] staged byte-interleaved: buf[w*4+j] = row_j[w].
// One LDS.32 at w*4 yields the 4 batch lookups for (o,k).
__global__ __launch_bounds__(1024, 1)
void lookup_kernel(const int* __restrict__ in_idx,
                   const float* __restrict__ scale_p,
                   const float* __restrict__ zp_p,
                   float* __restrict__ out) {
    __shared__ __align__(16) uint8_t buf[2][NIDX * BTILE];  // 2 x 16KB
    __shared__ uint32_t iidx[BTILE][KPOS];                  // 4KB

    const int tid = threadIdx.x;
    const int b0  = blockIdx.x * BTILE;

    {
        int j = tid >> 8;          // 0..3
        int k = tid & 255;         // 0..255
        int v = in_idx[(b0 + j) * KPOS + k];
        v = v < 0 ? 0 : (v > NIDX - 1 ? NIDX - 1 : v);
        iidx[j][k] = (uint32_t)v;
    }
    __syncthreads();

    const uint4* tab128 = (const uint4*)g_tab;  // rows = 256 uint4

    // ---- prologue: warp-group 0 stages k=0 into buf[0] ----
    if ((tid >> 8) == 0) {
        const int l = tid & 255;
        uint4 q[4];
#pragma unroll
        for (int j = 0; j < 4; j++)
            q[j] = tab128[iidx[j][0] * 256 + l];
#pragma unroll
        for (int s = 0; s < 4; s++) {
            uint32_t r0 = ((const uint32_t*)&q[0])[s];
            uint32_t r1 = ((const uint32_t*)&q[1])[s];
            uint32_t r2 = ((const uint32_t*)&q[2])[s];
            uint32_t r3 = ((const uint32_t*)&q[3])[s];
            uint32_t t0 = __byte_perm(r0, r1, 0x5140);
            uint32_t t1 = __byte_perm(r0, r1, 0x7362);
            uint32_t t2 = __byte_perm(r2, r3, 0x5140);
            uint32_t t3 = __byte_perm(r2, r3, 0x7362);
            uint4 o4;
            o4.x = __byte_perm(t0, t2, 0x5410);
            o4.y = __byte_perm(t0, t2, 0x7632);
            o4.z = __byte_perm(t1, t3, 0x5410);
            o4.w = __byte_perm(t1, t3, 0x7632);
            *(uint4*)&buf[0][64 * l + 16 * s] = o4;
        }
    }
    __syncthreads();

    uint32_t accLo = 0;  // packed u16: (batch b0+0, batch b0+1)
    uint32_t accHi = 0;  // packed u16: (batch b0+2, batch b0+3)
    int cur = 0;

    for (int k = 0; k < KPOS; k++) {
        const int nk = k + 1;
        const bool do_stage = (nk < KPOS) && ((tid >> 8) == (nk & 3));
        const int l = tid & 255;
        uint4 q[4];
        if (do_stage) {
#pragma unroll
            for (int j = 0; j < 4; j++)
                q[j] = tab128[iidx[j][nk] * 256 + l];
        }

        // ---- lookup for k from current buffer ----
        uint32_t w = (uint32_t)g_wT[k * OUTF + tid];      // coalesced u16
        uint32_t v = *(const uint32_t*)&buf[cur][w * 4];  // 4 batch bytes
        accLo = __vadd2(accLo, __byte_perm(v, 0, 0x4140));
        accHi = __vadd2(accHi, __byte_perm(v, 0, 0x4342));

        // ---- transpose + store k+1 into the other buffer ----
        if (do_stage) {
            uint8_t* nb = buf[cur ^ 1];
#pragma unroll
            for (int s = 0; s < 4; s++) {
                uint32_t r0 = ((const uint32_t*)&q[0])[s];
                uint32_t r1 = ((const uint32_t*)&q[1])[s];
                uint32_t r2 = ((const uint32_t*)&q[2])[s];
                uint32_t r3 = ((const uint32_t*)&q[3])[s];
                uint32_t t0 = __byte_perm(r0, r1, 0x5140);
                uint32_t t1 = __byte_perm(r0, r1, 0x7362);
                uint32_t t2 = __byte_perm(r2, r3, 0x5140);
                uint32_t t3 = __byte_perm(r2, r3, 0x7362);
                uint4 o4;
                o4.x = __byte_perm(t0, t2, 0x5410);
                o4.y = __byte_perm(t0, t2, 0x7632);
                o4.z = __byte_perm(t1, t3, 0x5410);
                o4.w = __byte_perm(t1, t3, 0x7632);
                *(uint4*)&nb[64 * l + 16 * s] = o4;
            }
        }
        __syncthreads();
        cur ^= 1;
    }

    // ---- epilogue: S -> (S - 256*zp)*scale ----
    const float scale = *scale_p;
    const float zp    = *zp_p;
    const float bias  = 256.0f * zp;
    out[(b0 + 0) * OUTF + tid] = ((float)(accLo & 0xFFFFu) - bias) * scale;
    out[(b0 + 1) * OUTF + tid] = ((float)(accLo >> 16)     - bias) * scale;
    out[(b0 + 2) * OUTF + tid] = ((float)(accHi & 0xFFFFu) - bias) * scale;
    out[(b0 + 3) * OUTF + tid] = ((float)(accHi >> 16)     - bias) * scale;
}

extern "C" void kernel_launch(void* const* d_in, const int* in_sizes, int n_in,
                              void* d_out, int out_size) {
    (void)in_sizes; (void)n_in; (void)out_size;
    const int*   in_idx = (const int*)d_in[0];
    const int*   w_idx  = (const int*)d_in[1];
    const void*  table  = (const void*)d_in[2];
    const float* scale  = (const float*)d_in[3];
    const float* zp     = (const float*)d_in[4];
    float*       outp   = (float*)d_out;

    detect_kernel<<<1, 32>>>((const uint32_t*)table);
    convert_kernel<<<(NIDX * NIDX / 16) / 256, 256>>>(table);
    prep_w_kernel<<<(OUTF * KPOS + 255) / 256, 256>>>(w_idx);
    lookup_kernel<<<BATCH / BTILE, 1024>>>(in_idx, scale, zp, outp);
}

// round 5
// speedup vs baseline: 1.7162x; 1.7162x over previous
#include <cuda_runtime.h>
#include <stdint.h>
#include <math.h>

#define BATCH 512
#define OUTF  1024
#define KPOS  256
#define NIDX  4096
#define BTILE 4

// ---- device scratch (no allocations allowed) ----
__device__ uint8_t  g_tab[NIDX * NIDX];           // 16MB compact u8 table
__device__ ushort4  g_w4[(KPOS / 4) * OUTF];      // w indices packed [kb][o] x4 k's
__device__ int      g_mode;                       // 0=u8, 1=int32, 2=float32

// -------- detect how the table was uploaded --------
__global__ void detect_kernel(const uint32_t* __restrict__ w) {
    int lane = threadIdx.x;
    bool small = true, isf = true;
    for (int i = lane; i < 1024; i += 32) {
        uint32_t x = w[i];
        small = small && (x < 256u);
        float f = __uint_as_float(x);
        isf = isf && (f >= 0.0f) && (f < 256.0f) && (f == truncf(f));
    }
    small = __all_sync(0xFFFFFFFFu, small);
    isf   = __all_sync(0xFFFFFFFFu, isf);
    if (lane == 0) g_mode = small ? 1 : (isf ? 2 : 0);
}

// -------- compact table -> u8 (16 bytes per thread) --------
__global__ void convert_kernel(const void* __restrict__ table) {
    const int mode = g_mode;
    const int t = blockIdx.x * blockDim.x + threadIdx.x;  // 1M threads
    uint4 o;
    if (mode == 1) {
        const int4* src = (const int4*)table;
        uint32_t p[4];
#pragma unroll
        for (int s = 0; s < 4; s++) {
            int4 v = src[t * 4 + s];
            p[s] = (uint32_t)(v.x & 255) | ((uint32_t)(v.y & 255) << 8) |
                   ((uint32_t)(v.z & 255) << 16) | ((uint32_t)(v.w & 255) << 24);
        }
        o = make_uint4(p[0], p[1], p[2], p[3]);
    } else if (mode == 2) {
        const float4* src = (const float4*)table;
        uint32_t p[4];
#pragma unroll
        for (int s = 0; s < 4; s++) {
            float4 v = src[t * 4 + s];
            p[s] = (uint32_t)v.x | ((uint32_t)v.y << 8) |
                   ((uint32_t)v.z << 16) | ((uint32_t)v.w << 24);
        }
        o = make_uint4(p[0], p[1], p[2], p[3]);
    } else {
        o = ((const uint4*)table)[t];
    }
    *(uint4*)&g_tab[t * 16] = o;
}

// -------- pre-pass: clamp + pack weight indices as ushort4 per 4-k block ----
__global__ void prep_w_kernel(const int* __restrict__ w_idx) {
    int t = blockIdx.x * blockDim.x + threadIdx.x;   // 64 * 1024
    int kb = t >> 10;
    int o  = t & 1023;
    int4 v = *(const int4*)&w_idx[o * KPOS + kb * 4];
    int a = v.x < 0 ? 0 : (v.x > NIDX - 1 ? NIDX - 1 : v.x);
    int b = v.y < 0 ? 0 : (v.y > NIDX - 1 ? NIDX - 1 : v.y);
    int c = v.z < 0 ? 0 : (v.z > NIDX - 1 ? NIDX - 1 : v.z);
    int d = v.w < 0 ? 0 : (v.w > NIDX - 1 ? NIDX - 1 : v.w);
    g_w4[t] = make_ushort4((uint16_t)a, (uint16_t)b, (uint16_t)c, (uint16_t)d);
}

// swizzle: XOR bits[4:5] with bits[7:8]; identical at store and gather (bijective)
__device__ __forceinline__ uint32_t sw(uint32_t a) {
    return a ^ ((a >> 3) & 0x30u);
}

// transpose 4 rows x 16B -> interleaved layout, store into buffer (swizzled)
__device__ __forceinline__ void transpose_store(uint8_t* bufp, int l, const uint4* q) {
#pragma unroll
    for (int s = 0; s < 4; s++) {
        uint32_t r0 = ((const uint32_t*)&q[0])[s];
        uint32_t r1 = ((const uint32_t*)&q[1])[s];
        uint32_t r2 = ((const uint32_t*)&q[2])[s];
        uint32_t r3 = ((const uint32_t*)&q[3])[s];
        uint32_t t0 = __byte_perm(r0, r1, 0x5140);
        uint32_t t1 = __byte_perm(r0, r1, 0x7362);
        uint32_t t2 = __byte_perm(r2, r3, 0x5140);
        uint32_t t3 = __byte_perm(r2, r3, 0x7362);
        uint4 o4;
        o4.x = __byte_perm(t0, t2, 0x5410);
        o4.y = __byte_perm(t0, t2, 0x7632);
        o4.z = __byte_perm(t1, t3, 0x5410);
        o4.w = __byte_perm(t1, t3, 0x7632);
        *(uint4*)(bufp + sw(64u * l + 16u * s)) = o4;
    }
}

// -------- main kernel --------
// CTA = 4 batches x 1024 outputs. Double buffer (2x16KB static smem).
// Warp-group g owns k with k%4==g: issues its 4 LDG.128s ~4 iterations early
// (held in registers), transpose-stores k at iteration k-1, everyone gathers
// one k per iteration. 1 barrier per k, nothing latency-bound inside it.
__global__ __launch_bounds__(1024, 1)
void lookup_kernel(const int* __restrict__ in_idx,
                   const float* __restrict__ scale_p,
                   const float* __restrict__ zp_p,
                   float* __restrict__ out) {
    __shared__ __align__(16) uint8_t  buf[2][NIDX * BTILE];  // 32KB
    __shared__ uint32_t iidx[BTILE][KPOS];                   // 4KB

    const int tid = threadIdx.x;
    const int wg  = tid >> 8;          // warp-group 0..3
    const int l   = tid & 255;         // 16B chunk within row
    const int b0  = blockIdx.x * BTILE;
    const uint4* tab128 = (const uint4*)g_tab;

    // stage input indices (clamped)
    {
        int v = in_idx[(b0 + wg) * KPOS + l];
        v = v < 0 ? 0 : (v > NIDX - 1 ? NIDX - 1 : v);
        iidx[wg][l] = (uint32_t)v;
    }
    __syncthreads();

    // ---- pipeline prologue ----
    // every group loads its first owned k (= wg) into registers;
    // groups 0,1 store k=0,1 into buf[0],buf[1] now and preload k=4,5.
    uint4 q[4];
#pragma unroll
    for (int j = 0; j < 4; j++)
        q[j] = tab128[iidx[j][wg] * 256 + l];
    if (wg < 2) {
        transpose_store(buf[wg], l, q);
#pragma unroll
        for (int j = 0; j < 4; j++)
            q[j] = tab128[iidx[j][wg + 4] * 256 + l];
    }
    __syncthreads();

    uint32_t accLo = 0;  // packed u16: (batch b0+0, b0+1)
    uint32_t accHi = 0;  // packed u16: (batch b0+2, b0+3)
    const int su = (wg - 1) & 3;   // unroll slot where this group stages

    for (int kb = 0; kb < KPOS / 4; kb++) {
        ushort4 w4 = g_w4[kb * OUTF + tid];
        uint16_t wv[4] = {w4.x, w4.y, w4.z, w4.w};
#pragma unroll
        for (int u = 0; u < 4; u++) {
            const int k = kb * 4 + u;
            // group (k+1)&3 stores k+1 into buf[(k+1)&1] (free this iter),
            // then issues LDGs for its next owned k (k+5) -> 4-deep pipeline.
            if (u == su && (k + 1) >= 2 && (k + 1) < KPOS) {
                transpose_store(buf[(k + 1) & 1], l, q);
                const int kn = k + 5;
                if (kn < KPOS) {
#pragma unroll
                    for (int j = 0; j < 4; j++)
                        q[j] = tab128[iidx[j][kn] * 256 + l];
                }
            }
            // gather k from current buffer
            uint32_t v = *(const uint32_t*)(buf[k & 1] + sw((uint32_t)wv[u] * 4u));
            accLo = __vadd2(accLo, __byte_perm(v, 0, 0x4140));
            accHi = __vadd2(accHi, __byte_perm(v, 0, 0x4342));
            __syncthreads();
        }
    }

    // ---- epilogue: S -> (S - 256*zp)*scale ----
    const float scale = *scale_p;
    const float zp    = *zp_p;
    const float bias  = 256.0f * zp;
    out[(b0 + 0) * OUTF + tid] = ((float)(accLo & 0xFFFFu) - bias) * scale;
    out[(b0 + 1) * OUTF + tid] = ((float)(accLo >> 16)     - bias) * scale;
    out[(b0 + 2) * OUTF + tid] = ((float)(accHi & 0xFFFFu) - bias) * scale;
    out[(b0 + 3) * OUTF + tid] = ((float)(accHi >> 16)     - bias) * scale;
}

extern "C" void kernel_launch(void* const* d_in, const int* in_sizes, int n_in,
                              void* d_out, int out_size) {
    (void)in_sizes; (void)n_in; (void)out_size;
    const int*   in_idx = (const int*)d_in[0];
    const int*   w_idx  = (const int*)d_in[1];
    const void*  table  = (const void*)d_in[2];
    const float* scale  = (const float*)d_in[3];
    const float* zp     = (const float*)d_in[4];
    float*       outp   = (float*)d_out;

    detect_kernel<<<1, 32>>>((const uint32_t*)table);
    convert_kernel<<<(NIDX * NIDX / 16) / 256, 256>>>(table);
    prep_w_kernel<<<(OUTF * KPOS / 4) / 256, 256>>>(w_idx);
    lookup_kernel<<<BATCH / BTILE, 1024>>>(in_idx, scale, zp, outp);
}

// round 8
// speedup vs baseline: 2.0309x; 1.1834x over previous
#include <cuda_runtime.h>
#include <stdint.h>
#include <math.h>

#define BATCH 512
#define OUTF  1024
#define KPOS  256
#define KHALF 128
#define NIDX  4096
#define BTILE 4

// ---- device scratch (no allocations allowed) ----
__device__ uint8_t  g_tab[NIDX * NIDX];           // 16MB compact u8 table
__device__ ushort4  g_w4[(KPOS / 4) * OUTF];      // w indices packed [kb][o] x4 k's
__device__ uint4    g_part[128 * OUTF];           // partials per (bg,o): 2MB
__device__ int      g_mode;                       // 0=u8, 1=int32, 2=float32

// -------- detect how the table was uploaded --------
__global__ void detect_kernel(const uint32_t* __restrict__ w) {
    int lane = threadIdx.x;
    bool small = true, isf = true;
    for (int i = lane; i < 1024; i += 32) {
        uint32_t x = w[i];
        small = small && (x < 256u);
        float f = __uint_as_float(x);
        isf = isf && (f >= 0.0f) && (f < 256.0f) && (f == truncf(f));
    }
    small = __all_sync(0xFFFFFFFFu, small);
    isf   = __all_sync(0xFFFFFFFFu, isf);
    if (lane == 0) g_mode = small ? 1 : (isf ? 2 : 0);
}

// -------- compact table -> u8 (16 bytes per thread) --------
__global__ void convert_kernel(const void* __restrict__ table) {
    const int mode = g_mode;
    const int t = blockIdx.x * blockDim.x + threadIdx.x;  // 1M threads
    uint4 o;
    if (mode == 1) {
        const int4* src = (const int4*)table;
        uint32_t p[4];
#pragma unroll
        for (int s = 0; s < 4; s++) {
            int4 v = src[t * 4 + s];
            p[s] = (uint32_t)(v.x & 255) | ((uint32_t)(v.y & 255) << 8) |
                   ((uint32_t)(v.z & 255) << 16) | ((uint32_t)(v.w & 255) << 24);
        }
        o = make_uint4(p[0], p[1], p[2], p[3]);
    } else if (mode == 2) {
        const float4* src = (const float4*)table;
        uint32_t p[4];
#pragma unroll
        for (int s = 0; s < 4; s++) {
            float4 v = src[t * 4 + s];
            p[s] = (uint32_t)v.x | ((uint32_t)v.y << 8) |
                   ((uint32_t)v.z << 16) | ((uint32_t)v.w << 24);
        }
        o = make_uint4(p[0], p[1], p[2], p[3]);
    } else {
        o = ((const uint4*)table)[t];
    }
    *(uint4*)&g_tab[t * 16] = o;
}

// -------- pre-pass: clamp + pack weight indices as ushort4 per 4-k block ----
__global__ void prep_w_kernel(const int* __restrict__ w_idx) {
    int t = blockIdx.x * blockDim.x + threadIdx.x;   // 64 * 1024
    int kb = t >> 10;
    int o  = t & 1023;
    int4 v = *(const int4*)&w_idx[o * KPOS + kb * 4];
    int a = v.x < 0 ? 0 : (v.x > NIDX - 1 ? NIDX - 1 : v.x);
    int b = v.y < 0 ? 0 : (v.y > NIDX - 1 ? NIDX - 1 : v.y);
    int c = v.z < 0 ? 0 : (v.z > NIDX - 1 ? NIDX - 1 : v.z);
    int d = v.w < 0 ? 0 : (v.w > NIDX - 1 ? NIDX - 1 : v.w);
    g_w4[t] = make_ushort4((uint16_t)a, (uint16_t)b, (uint16_t)c, (uint16_t)d);
}

// swizzle: XOR bits[4:5] with bits[7:8]; identical at store and gather (bijective)
__device__ __forceinline__ uint32_t sw(uint32_t a) {
    return a ^ ((a >> 3) & 0x30u);
}

// transpose 4 rows x 16B -> interleaved layout, store into buffer (swizzled)
__device__ __forceinline__ void transpose_store(uint8_t* bufp, int l, const uint4* q) {
#pragma unroll
    for (int s = 0; s < 4; s++) {
        uint32_t r0 = ((const uint32_t*)&q[0])[s];
        uint32_t r1 = ((const uint32_t*)&q[1])[s];
        uint32_t r2 = ((const uint32_t*)&q[2])[s];
        uint32_t r3 = ((const uint32_t*)&q[3])[s];
        uint32_t t0 = __byte_perm(r0, r1, 0x5140);
        uint32_t t1 = __byte_perm(r0, r1, 0x7362);
        uint32_t t2 = __byte_perm(r2, r3, 0x5140);
        uint32_t t3 = __byte_perm(r2, r3, 0x7362);
        uint4 o4;
        o4.x = __byte_perm(t0, t2, 0x5410);
        o4.y = __byte_perm(t0, t2, 0x7632);
        o4.z = __byte_perm(t1, t3, 0x5410);
        o4.w = __byte_perm(t1, t3, 0x7632);
        *(uint4*)(bufp + sw(64u * l + 16u * s)) = o4;
    }
}

// -------- main kernel --------
// CTA = 512 threads, 4 batches x 1024 outputs (2 per thread) x HALF the k's.
// grid = 128 batch-groups x 2 k-halves -> 2 CTAs resident per SM so one CTA's
// barrier stalls overlap the other's issue. 2 warp-groups; group g owns local
// k%2==g, preloads 2 iterations ahead into registers, stores k+1 at iter k.
__global__ __launch_bounds__(512, 2)
void lookup_kernel(const int* __restrict__ in_idx) {
    __shared__ __align__(16) uint8_t  buf[2][NIDX * BTILE];  // 32KB
    __shared__ uint32_t iidx[BTILE][KHALF];                  // 2KB

    const int tid = threadIdx.x;
    const int wg  = tid >> 8;          // warp-group 0..1
    const int l   = tid & 255;         // 16B chunk within row
    const int bg  = blockIdx.x >> 1;
    const int kh  = blockIdx.x & 1;
    const int k0  = kh * KHALF;
    const int b0  = bg * BTILE;
    const uint4* tab128 = (const uint4*)g_tab;

    // stage this half's input indices (clamped): 512 threads cover 4x128
    {
        int j  = tid >> 7;
        int kk = tid & 127;
        int v = in_idx[(b0 + j) * KPOS + k0 + kk];
        v = v < 0 ? 0 : (v > NIDX - 1 ? NIDX - 1 : v);
        iidx[j][kk] = (uint32_t)v;
    }
    __syncthreads();

    // ---- pipeline prologue ----
    // group g preloads its first owned local k (= wg); group 0 stores k=0
    // now and preloads k=2.
    uint4 q[4];
#pragma unroll
    for (int j = 0; j < 4; j++)
        q[j] = tab128[iidx[j][wg] * 256 + l];
    if (wg == 0) {
        transpose_store(buf[0], l, q);
#pragma unroll
        for (int j = 0; j < 4; j++)
            q[j] = tab128[iidx[j][2] * 256 + l];
    }
    __syncthreads();

    uint32_t accLo0 = 0, accHi0 = 0;   // output o = tid
    uint32_t accLo1 = 0, accHi1 = 0;   // output o = tid + 512

    for (int kb = 0; kb < KHALF / 4; kb++) {
        const int gkb = kh * (KHALF / 4) + kb;
        ushort4 w4a = g_w4[gkb * OUTF + tid];
        ushort4 w4b = g_w4[gkb * OUTF + tid + 512];
        uint16_t wa[4] = {w4a.x, w4a.y, w4a.z, w4a.w};
        uint16_t wb[4] = {w4b.x, w4b.y, w4b.z, w4b.w};
#pragma unroll
        for (int u = 0; u < 4; u++) {
            const int k = kb * 4 + u;
            // group (k+1)&1 stores k+1 (preloaded 2 iters ago), then preloads k+3
            if (((u + 1) & 1) == wg && (k + 1) < KHALF) {
                transpose_store(buf[(k + 1) & 1], l, q);
                const int kn = k + 3;
                if (kn < KHALF) {
#pragma unroll
                    for (int j = 0; j < 4; j++)
                        q[j] = tab128[iidx[j][kn] * 256 + l];
                }
            }
            // gather k for both outputs from current buffer
            const uint8_t* bp = buf[k & 1];
            uint32_t va = *(const uint32_t*)(bp + sw((uint32_t)wa[u] * 4u));
            uint32_t vb = *(const uint32_t*)(bp + sw((uint32_t)wb[u] * 4u));
            accLo0 = __vadd2(accLo0, __byte_perm(va, 0, 0x4140));
            accHi0 = __vadd2(accHi0, __byte_perm(va, 0, 0x4342));
            accLo1 = __vadd2(accLo1, __byte_perm(vb, 0, 0x4140));
            accHi1 = __vadd2(accHi1, __byte_perm(vb, 0, 0x4342));
            __syncthreads();
        }
    }

    // ---- write packed u16 partials (deterministic; no atomics) ----
    // g_part[bg*OUTF + o] = {h0.Lo, h0.Hi, h1.Lo, h1.Hi}; the two k-half CTAs
    // write disjoint 8-byte halves of each uint4 (kh=0 -> .x.y, kh=1 -> .z.w).
    uint32_t* gp = (uint32_t*)g_part;
    uint32_t base0 = (uint32_t)(bg * OUTF + tid) * 4u + (uint32_t)kh * 2u;
    uint32_t base1 = (uint32_t)(bg * OUTF + tid + 512) * 4u + (uint32_t)kh * 2u;
    gp[base0]     = accLo0;
    gp[base0 + 1] = accHi0;
    gp[base1]     = accLo1;
    gp[base1 + 1] = accHi1;
}

// -------- reduce: combine k-halves, dequantize, write out --------
__global__ __launch_bounds__(256)
void reduce_kernel(const float* __restrict__ scale_p,
                   const float* __restrict__ zp_p,
                   float* __restrict__ out) {
    int t  = blockIdx.x * blockDim.x + threadIdx.x;   // 128*1024
    int bg = t >> 10;
    int o  = t & 1023;
    uint4 p = g_part[bg * OUTF + o];                  // one LDG.128
    uint32_t Lo = __vadd2(p.x, p.z);   // u16 sums <= 65280, no overflow
    uint32_t Hi = __vadd2(p.y, p.w);
    const float scale = *scale_p;
    const float zp    = *zp_p;
    const float bias  = 256.0f * zp;
    int b0 = bg * BTILE;
    out[(b0 + 0) * OUTF + o] = ((float)(Lo & 0xFFFFu) - bias) * scale;
    out[(b0 + 1) * OUTF + o] = ((float)(Lo >> 16)     - bias) * scale;
    out[(b0 + 2) * OUTF + o] = ((float)(Hi & 0xFFFFu) - bias) * scale;
    out[(b0 + 3) * OUTF + o] = ((float)(Hi >> 16)     - bias) * scale;
}

extern "C" void kernel_launch(void* const* d_in, const int* in_sizes, int n_in,
                              void* d_out, int out_size) {
    (void)in_sizes; (void)n_in; (void)out_size;
    const int*   in_idx = (const int*)d_in[0];
    const int*   w_idx  = (const int*)d_in[1];
    const void*  table  = (const void*)d_in[2];
    const float* scale  = (const float*)d_in[3];
    const float* zp     = (const float*)d_in[4];
    float*       outp   = (float*)d_out;

    detect_kernel<<<1, 32>>>((const uint32_t*)table);
    convert_kernel<<<(NIDX * NIDX / 16) / 256, 256>>>(table);
    prep_w_kernel<<<(OUTF * KPOS / 4) / 256, 256>>>(w_idx);
    lookup_kernel<<<2 * (BATCH / BTILE), 512>>>(in_idx);
    reduce_kernel<<<(128 * OUTF) / 256, 256>>>(scale, zp, outp);
}

// round 9
// speedup vs baseline: 2.2064x; 1.0864x over previous
#include <cuda_runtime.h>
#include <stdint.h>
#include <math.h>

#define BATCH 512
#define OUTF  1024
#define KPOS  256
#define KHALF 128
#define NIDX  4096
#define BTILE 4

// ---- device scratch (no allocations allowed) ----
__device__ uint8_t  g_tab[NIDX * NIDX];           // 16MB compact u8 table
__device__ ushort4  g_w4[(KPOS / 4) * OUTF];      // PRE-SWIZZLED byte offsets [kb][o]
__device__ uint4    g_part[128 * OUTF];           // partials per (bg,o): 2MB
__device__ int      g_mode;                       // 0=u8, 1=int32, 2=float32

// -------- detect how the table was uploaded (vectorized, MLP=8) --------
__global__ void detect_kernel(const uint4* __restrict__ w) {
    int lane = threadIdx.x;
    bool small = true, isf = true;
#pragma unroll
    for (int i = 0; i < 8; i++) {
        uint4 x4 = w[lane + i * 32];
        uint32_t xs[4] = {x4.x, x4.y, x4.z, x4.w};
#pragma unroll
        for (int j = 0; j < 4; j++) {
            uint32_t x = xs[j];
            small = small && (x < 256u);
            float f = __uint_as_float(x);
            isf = isf && (f >= 0.0f) && (f < 256.0f) && (f == truncf(f));
        }
    }
    small = __all_sync(0xFFFFFFFFu, small);
    isf   = __all_sync(0xFFFFFFFFu, isf);
    if (lane == 0) g_mode = small ? 1 : (isf ? 2 : 0);
}

// -------- compact table -> u8 (16 bytes per thread) --------
__global__ void convert_kernel(const void* __restrict__ table) {
    const int mode = g_mode;
    const int t = blockIdx.x * blockDim.x + threadIdx.x;  // 1M threads
    uint4 o;
    if (mode == 1) {
        const int4* src = (const int4*)table;
        uint32_t p[4];
#pragma unroll
        for (int s = 0; s < 4; s++) {
            int4 v = src[t * 4 + s];
            p[s] = (uint32_t)(v.x & 255) | ((uint32_t)(v.y & 255) << 8) |
                   ((uint32_t)(v.z & 255) << 16) | ((uint32_t)(v.w & 255) << 24);
        }
        o = make_uint4(p[0], p[1], p[2], p[3]);
    } else if (mode == 2) {
        const float4* src = (const float4*)table;
        uint32_t p[4];
#pragma unroll
        for (int s = 0; s < 4; s++) {
            float4 v = src[t * 4 + s];
            p[s] = (uint32_t)v.x | ((uint32_t)v.y << 8) |
                   ((uint32_t)v.z << 16) | ((uint32_t)v.w << 24);
        }
        o = make_uint4(p[0], p[1], p[2], p[3]);
    } else {
        o = ((const uint4*)table)[t];
    }
    *(uint4*)&g_tab[t * 16] = o;
}

// swizzle: XOR bits[4:5] with bits[7:8]; bijective within 16KB
__device__ __host__ __forceinline__ uint32_t sw(uint32_t a) {
    return a ^ ((a >> 3) & 0x30u);
}

// -------- pre-pass: clamp, scale x4, PRE-SWIZZLE, pack as ushort4 --------
__global__ void prep_w_kernel(const int* __restrict__ w_idx) {
    int t = blockIdx.x * blockDim.x + threadIdx.x;   // 64 * 1024
    int kb = t >> 10;
    int o  = t & 1023;
    int4 v = *(const int4*)&w_idx[o * KPOS + kb * 4];
    uint32_t a = (uint32_t)(v.x < 0 ? 0 : (v.x > NIDX - 1 ? NIDX - 1 : v.x)) * 4u;
    uint32_t b = (uint32_t)(v.y < 0 ? 0 : (v.y > NIDX - 1 ? NIDX - 1 : v.y)) * 4u;
    uint32_t c = (uint32_t)(v.z < 0 ? 0 : (v.z > NIDX - 1 ? NIDX - 1 : v.z)) * 4u;
    uint32_t d = (uint32_t)(v.w < 0 ? 0 : (v.w > NIDX - 1 ? NIDX - 1 : v.w)) * 4u;
    g_w4[t] = make_ushort4((uint16_t)sw(a), (uint16_t)sw(b),
                           (uint16_t)sw(c), (uint16_t)sw(d));
}

// transpose 4 rows x 16B -> interleaved layout, store (precomputed swizzled addrs)
__device__ __forceinline__ void transpose_store(uint8_t* bufp, const uint32_t* sa,
                                                const uint4* q) {
#pragma unroll
    for (int s = 0; s < 4; s++) {
        uint32_t r0 = ((const uint32_t*)&q[0])[s];
        uint32_t r1 = ((const uint32_t*)&q[1])[s];
        uint32_t r2 = ((const uint32_t*)&q[2])[s];
        uint32_t r3 = ((const uint32_t*)&q[3])[s];
        uint32_t t0 = __byte_perm(r0, r1, 0x5140);
        uint32_t t1 = __byte_perm(r0, r1, 0x7362);
        uint32_t t2 = __byte_perm(r2, r3, 0x5140);
        uint32_t t3 = __byte_perm(r2, r3, 0x7362);
        uint4 o4;
        o4.x = __byte_perm(t0, t2, 0x5410);
        o4.y = __byte_perm(t0, t2, 0x7632);
        o4.z = __byte_perm(t1, t3, 0x5410);
        o4.w = __byte_perm(t1, t3, 0x7632);
        *(uint4*)(bufp + sa[s]) = o4;
    }
}

// -------- main kernel --------
// CTA = 512 thr, 4 batches x 1024 outputs (2/thread) x half the k's; 2 CTAs/SM.
// Balanced roles per iteration k: group (k+1)&1 transpose-STORES k+1 (preloaded
// last iter); the other group issues LDG preloads of k+2 (which it owns). Every
// warp has near-equal L1 work per barrier interval.
__global__ __launch_bounds__(512, 2)
void lookup_kernel(const int* __restrict__ in_idx) {
    __shared__ __align__(16) uint8_t  buf[2][NIDX * BTILE];  // 32KB
    __shared__ uint32_t iidx[BTILE][KHALF];                  // 2KB

    const int tid = threadIdx.x;
    const int wg  = tid >> 8;          // warp-group 0..1
    const int l   = tid & 255;         // 16B chunk within row
    const int bg  = blockIdx.x >> 1;
    const int kh  = blockIdx.x & 1;
    const int b0  = bg * BTILE;
    const uint4* tab128 = (const uint4*)g_tab;

    // stage this half's input indices (clamped): 512 threads cover 4x128
    {
        int j  = tid >> 7;
        int kk = tid & 127;
        int v = in_idx[(b0 + j) * KPOS + kh * KHALF + kk];
        v = v < 0 ? 0 : (v > NIDX - 1 ? NIDX - 1 : v);
        iidx[j][kk] = (uint32_t)v;
    }
    __syncthreads();

    // precomputed swizzled store addresses for this thread's 4 chunks
    uint32_t sa[4];
#pragma unroll
    for (int s = 0; s < 4; s++) sa[s] = sw(64u * l + 16u * s);

    // ---- prologue ----
    // group 0: load k=0, store into buf[0]. group 1: preload k=1 (stores iter 0).
    uint4 q[4];
    {
        const int kfirst = (wg == 0) ? 0 : 1;
#pragma unroll
        for (int j = 0; j < 4; j++)
            q[j] = tab128[iidx[j][kfirst] * 256 + l];
        if (wg == 0) transpose_store(buf[0], sa, q);
    }
    __syncthreads();

    uint32_t accLo0 = 0, accHi0 = 0;   // output o = tid
    uint32_t accLo1 = 0, accHi1 = 0;   // output o = tid + 512

    for (int kb = 0; kb < KHALF / 4; kb++) {
        const int gkb = kh * (KHALF / 4) + kb;
        ushort4 w4a = g_w4[gkb * OUTF + tid];          // pre-swizzled offsets
        ushort4 w4b = g_w4[gkb * OUTF + tid + 512];
        uint16_t wa[4] = {w4a.x, w4a.y, w4a.z, w4a.w};
        uint16_t wb[4] = {w4b.x, w4b.y, w4b.z, w4b.w};
#pragma unroll
        for (int u = 0; u < 4; u++) {
            const int k = kb * 4 + u;
            if (((k + 1) & 1) == wg) {
                // this group stores k+1 (held in q since last iteration)
                if (k + 1 < KHALF)
                    transpose_store(buf[(k + 1) & 1], sa, q);
            } else {
                // other group preloads k+2 (it stores it next iteration)
                if (k + 2 < KHALF) {
#pragma unroll
                    for (int j = 0; j < 4; j++)
                        q[j] = tab128[iidx[j][k + 2] * 256 + l];
                }
            }
            // gather k for both outputs from current buffer
            const uint8_t* bp = buf[k & 1];
            uint32_t va = *(const uint32_t*)(bp + wa[u]);
            uint32_t vb = *(const uint32_t*)(bp + wb[u]);
            accLo0 = __vadd2(accLo0, __byte_perm(va, 0, 0x4140));
            accHi0 = __vadd2(accHi0, __byte_perm(va, 0, 0x4342));
            accLo1 = __vadd2(accLo1, __byte_perm(vb, 0, 0x4140));
            accHi1 = __vadd2(accHi1, __byte_perm(vb, 0, 0x4342));
            __syncthreads();
        }
    }

    // ---- write packed u16 partials (disjoint 8B halves per kh; no atomics) ----
    uint32_t* gp = (uint32_t*)g_part;
    uint32_t base0 = (uint32_t)(bg * OUTF + tid) * 4u + (uint32_t)kh * 2u;
    uint32_t base1 = (uint32_t)(bg * OUTF + tid + 512) * 4u + (uint32_t)kh * 2u;
    gp[base0]     = accLo0;
    gp[base0 + 1] = accHi0;
    gp[base1]     = accLo1;
    gp[base1 + 1] = accHi1;
}

// -------- reduce: combine k-halves, dequantize, write out --------
__global__ __launch_bounds__(256)
void reduce_kernel(const float* __restrict__ scale_p,
                   const float* __restrict__ zp_p,
                   float* __restrict__ out) {
    int t  = blockIdx.x * blockDim.x + threadIdx.x;   // 128*1024
    int bg = t >> 10;
    int o  = t & 1023;
    uint4 p = g_part[bg * OUTF + o];                  // one LDG.128
    uint32_t Lo = __vadd2(p.x, p.z);   // u16 sums <= 65280, no overflow
    uint32_t Hi = __vadd2(p.y, p.w);
    const float scale = *scale_p;
    const float zp    = *zp_p;
    const float bias  = 256.0f * zp;
    int b0 = bg * BTILE;
    out[(b0 + 0) * OUTF + o] = ((float)(Lo & 0xFFFFu) - bias) * scale;
    out[(b0 + 1) * OUTF + o] = ((float)(Lo >> 16)     - bias) * scale;
    out[(b0 + 2) * OUTF + o] = ((float)(Hi & 0xFFFFu) - bias) * scale;
    out[(b0 + 3) * OUTF + o] = ((float)(Hi >> 16)     - bias) * scale;
}

extern "C" void kernel_launch(void* const* d_in, const int* in_sizes, int n_in,
                              void* d_out, int out_size) {
    (void)in_sizes; (void)n_in; (void)out_size;
    const int*   in_idx = (const int*)d_in[0];
    const int*   w_idx  = (const int*)d_in[1];
    const void*  table  = (const void*)d_in[2];
    const float* scale  = (const float*)d_in[3];
    const float* zp     = (const float*)d_in[4];
    float*       outp   = (float*)d_out;

    detect_kernel<<<1, 32>>>((const uint4*)table);
    convert_kernel<<<(NIDX * NIDX / 16) / 256, 256>>>(table);
    prep_w_kernel<<<(OUTF * KPOS / 4) / 256, 256>>>(w_idx);
    lookup_kernel<<<2 * (BATCH / BTILE), 512>>>(in_idx);
    reduce_kernel<<<(128 * OUTF) / 256, 256>>>(scale, zp, outp);
}